// round 8
// baseline (speedup 1.0000x reference)
#include <cuda_runtime.h>
#include <cstdint>

#define BS   2
#define SEQ  4096
#define HH   32
#define LLC  64
#define CC   (SEQ/LLC)   // 64
#define RS   72          // smem row stride in 4B words
#define GSTR (HH*64)

__device__ float g_states[(size_t)BS*CC*HH*64*64]; // [b][c][h][p][n]
__device__ float g_prefix[(size_t)BS*CC*HH*64*64];

typedef unsigned int u32;

__device__ __forceinline__ u32 cvt_tf32(float f){
    u32 u; asm("cvt.rna.tf32.f32 %0,%1;" : "=r"(u) : "f"(f)); return u;
}
__device__ __forceinline__ void mma8(float* d, const u32* a, u32 b0, u32 b1){
    asm volatile("mma.sync.aligned.m16n8k8.row.col.f32.tf32.tf32.f32 "
        "{%0,%1,%2,%3}, {%4,%5,%6,%7}, {%8,%9}, {%0,%1,%2,%3};"
        : "+f"(d[0]), "+f"(d[1]), "+f"(d[2]), "+f"(d[3])
        : "r"(a[0]), "r"(a[1]), "r"(a[2]), "r"(a[3]), "r"(b0), "r"(b1));
}

// skewed-paired layout: element (r,k) at word r*RS + W(r,k).
// pair q = 4*(k>>3)+(k&3) in [0,32) holds k (slot (k>>2)&1==0) and k+4 (slot 1);
// pair column rotated by r>>2.
__device__ __forceinline__ int Wf(int r, int k){
    return 2*(((4*(k>>3)) + (k&3) + (r>>2)) & 31) + ((k>>2)&1);
}
__device__ __forceinline__ void stp(u32* t, int r, int k, u32 v){
    t[r*RS + Wf(r,k)] = v;
}
__device__ __forceinline__ uint2 ldpair(const u32* t, int r, int kk, int qc){
    return *(const uint2*)&t[r*RS + 2*((4*kk + qc + (r>>2)) & 31)];
}
__device__ __forceinline__ void ldfragA(const u32* t, int r, int kk, int qc, u32* a){
    uint2 lo = ldpair(t, r, kk, qc), hi = ldpair(t, r+8, kk, qc);
    a[0] = lo.x; a[1] = hi.x; a[2] = lo.y; a[3] = hi.y;
}

// ===========================================================================
// K1: per (b,c,h): Y_diag -> Y, chunk states -> g_states. 128 thr, 2x2 roles.
// ===========================================================================
__global__ __launch_bounds__(128, 4) void ssd_k1(
    const float* __restrict__ X, const float* __restrict__ A,
    const float* __restrict__ Bm, const float* __restrict__ Cm,
    float* __restrict__ Y)
{
    extern __shared__ float smf[];
    u32* sXt = (u32*)smf;              // [p][s] skew; later sSt stage (plain)
    u32* sB  = (u32*)smf + 64*RS;      // [s][n] skew; later sY stage (plain)
    u32* sC  = (u32*)smf + 2*64*RS;    // [l][n] skew -> sG [l][s] -> sBt [n][l]
    float* aA   = smf + 3*64*RS;
    float* el   = aA + 64;
    float* einv = el + 64;
    float* decs = einv + 64;
    u32*   sG   = sC;
    u32*   sBt  = sC;
    float* sY   = (float*)sB;
    float* sSt  = (float*)sXt;

    const int h = blockIdx.x, c = blockIdx.y, b = blockIdx.z;
    const int tid = threadIdx.x, wid = tid >> 5, lane = tid & 31;
    const int qr = lane >> 2, qc = lane & 3;
    const int base = ((b*SEQ + c*LLC)*HH + h)*64;

    // role rotation balances SMSPs across co-resident blocks
    const int rho = (wid + h + c) & 3;
    const int rh = rho >> 1, ch = rho & 1;
    const int rA0 = rh*32, rA1 = rh*32 + 16;
    const int cB = ch*32;

    // phase 0: load tiles (tf32), X transposed into sXt
    #pragma unroll
    for (int i = tid; i < 1024; i += 128) {
        int row = i >> 4, c4 = (i & 15) << 2;
        int g = base + row*GSTR + c4;
        float4 xv = *(const float4*)&X[g];
        float4 bv = *(const float4*)&Bm[g];
        float4 cv = *(const float4*)&Cm[g];
        stp(sB, row, c4+0, cvt_tf32(bv.x)); stp(sB, row, c4+1, cvt_tf32(bv.y));
        stp(sB, row, c4+2, cvt_tf32(bv.z)); stp(sB, row, c4+3, cvt_tf32(bv.w));
        stp(sC, row, c4+0, cvt_tf32(cv.x)); stp(sC, row, c4+1, cvt_tf32(cv.y));
        stp(sC, row, c4+2, cvt_tf32(cv.z)); stp(sC, row, c4+3, cvt_tf32(cv.w));
        stp(sXt, c4+0, row, cvt_tf32(xv.x)); stp(sXt, c4+1, row, cvt_tf32(xv.y));
        stp(sXt, c4+2, row, cvt_tf32(xv.z)); stp(sXt, c4+3, row, cvt_tf32(xv.w));
    }
    if (tid < 64) aA[tid] = A[(b*SEQ + c*LLC + tid)*HH + h];
    __syncthreads();

    if (tid < 64) {
        float s = 0.f, mine = 0.f;
        #pragma unroll
        for (int j = 0; j < 64; j++) { s += aA[j]; if (j == tid) mine = s; }
        el[tid]   = __expf(mine);
        einv[tid] = __expf(-mine);
        decs[tid] = __expf(s - mine);
    }
    __syncthreads();

    // ---- mm1: G[l,s] = sum_n C[l,n]*B[s,n]; skip all-above-diag tiles ----
    const bool needA0 = (cB <= rA0 + 15);   // any kept tile in rowgroup 0
    const bool needA1 = (cB <= rA1 + 15);
    float g[2][4][4] = {};
    #pragma unroll
    for (int kk = 0; kk < 8; kk++) {
        u32 a0[4], a1[4];
        if (needA0) ldfragA(sC, rA0+qr, kk, qc, a0);
        if (needA1) ldfragA(sC, rA1+qr, kk, qc, a1);
        #pragma unroll
        for (int t = 0; t < 4; t++) {
            int c0 = cB + t*8;
            bool k0 = (c0 <= rA0 + 15), k1 = (c0 <= rA1 + 15);
            if (k0 | k1) {
                uint2 bb = ldpair(sB, c0+qr, kk, qc);
                if (k0) mma8(g[0][t], a0, bb.x, bb.y);
                if (k1) mma8(g[1][t], a1, bb.x, bb.y);
            }
        }
    }
    __syncthreads();   // mm1 reads of sC/sB done

    // mask + decay into sG (only tiles mm2 will read)
    #pragma unroll
    for (int mg = 0; mg < 2; mg++) {
        int r0 = rh*32 + mg*16;
        int l0v = r0 + qr, l1v = l0v + 8;
        float e0 = el[l0v], e1 = el[l1v];
        #pragma unroll
        for (int t = 0; t < 4; t++) {
            int c0 = cB + t*8;
            if (c0 <= r0 + 15) {
                int s0 = c0 + 2*qc, s1 = s0 + 1;
                float i0 = einv[s0], i1 = einv[s1];
                float v0 = (s0 <= l0v) ? g[mg][t][0]*e0*i0 : 0.f;
                float v1 = (s1 <= l0v) ? g[mg][t][1]*e0*i1 : 0.f;
                float v2 = (s0 <= l1v) ? g[mg][t][2]*e1*i0 : 0.f;
                float v3 = (s1 <= l1v) ? g[mg][t][3]*e1*i1 : 0.f;
                stp(sG, l0v, s0, cvt_tf32(v0)); stp(sG, l0v, s1, cvt_tf32(v1));
                stp(sG, l1v, s0, cvt_tf32(v2)); stp(sG, l1v, s1, cvt_tf32(v3));
            }
        }
    }
    __syncthreads();

    // ---- mm2: Y[l,p] = sum_s G[l,s]*X[s,p]; skip zero k-ranges ----
    float y[2][4][4] = {};
    #pragma unroll
    for (int kk = 0; kk < 8; kk++) {
        bool m0 = (8*kk <= rA0 + 15), m1 = (8*kk <= rA1 + 15);
        u32 a0[4], a1[4];
        if (m0) ldfragA(sG, rA0+qr, kk, qc, a0);
        if (m1) ldfragA(sG, rA1+qr, kk, qc, a1);
        if (m1) {
            #pragma unroll
            for (int t = 0; t < 4; t++) {
                uint2 bb = ldpair(sXt, cB + t*8 + qr, kk, qc);
                if (m0) mma8(y[0][t], a0, bb.x, bb.y);
                mma8(y[1][t], a1, bb.x, bb.y);
            }
        }
    }
    __syncthreads();   // mm2 reads of sG done

    // build sBt[n][l] = tf32( B[l][n]*dec[l] ) into sC region
    #pragma unroll
    for (int i = tid; i < 2048; i += 128) {
        int l = i >> 5, q = i & 31;
        uint2 bb = *(const uint2*)&sB[l*RS + 2*((q + (l>>2)) & 31)];
        int n_lo = 8*(q>>2) + (q&3), n_hi = n_lo + 4;
        float d = decs[l];
        stp(sBt, n_lo, l, cvt_tf32(__uint_as_float(bb.x)*d));
        stp(sBt, n_hi, l, cvt_tf32(__uint_as_float(bb.y)*d));
    }
    __syncthreads();

    // ---- mm3: S[p,n] = sum_l Xt[p,l]*(dec[l]*B[l,n]) ----
    float st[2][4][4] = {};
    #pragma unroll
    for (int kk = 0; kk < 8; kk++) {
        u32 a0[4], a1[4];
        ldfragA(sXt, rA0+qr, kk, qc, a0);
        ldfragA(sXt, rA1+qr, kk, qc, a1);
        #pragma unroll
        for (int t = 0; t < 4; t++) {
            uint2 bb = ldpair(sBt, cB + t*8 + qr, kk, qc);
            mma8(st[0][t], a0, bb.x, bb.y);
            mma8(st[1][t], a1, bb.x, bb.y);
        }
    }
    __syncthreads();   // mm3 reads of sXt/sBt done

    // stage results (plain row-major, stride RS)
    #pragma unroll
    for (int mg = 0; mg < 2; mg++) {
        int r0 = rh*32 + mg*16;
        #pragma unroll
        for (int t = 0; t < 4; t++) {
            int c0 = cB + t*8 + 2*qc;
            *(float2*)&sY[(r0+qr)*RS + c0]    = make_float2(y[mg][t][0], y[mg][t][1]);
            *(float2*)&sY[(r0+qr+8)*RS + c0]  = make_float2(y[mg][t][2], y[mg][t][3]);
            *(float2*)&sSt[(r0+qr)*RS + c0]   = make_float2(st[mg][t][0], st[mg][t][1]);
            *(float2*)&sSt[(r0+qr+8)*RS + c0] = make_float2(st[mg][t][2], st[mg][t][3]);
        }
    }
    __syncthreads();

    const int sbase = ((b*CC + c)*HH + h)*4096;
    #pragma unroll
    for (int i = tid; i < 1024; i += 128) {
        int row = i >> 4, c4 = (i & 15) << 2;
        *(float4*)&Y[base + row*GSTR + c4] = *(const float4*)&sY[row*RS + c4];
        *(float4*)&g_states[sbase + row*64 + c4] = *(const float4*)&sSt[row*RS + c4];
    }
}

// ===========================================================================
// K2: inter-chunk scan, 512 blocks (8 segments per (b,h)), prefetched
// ===========================================================================
__global__ __launch_bounds__(512) void ssd_k2(const float* __restrict__ A)
{
    __shared__ float ea[CC];
    const int blk = blockIdx.x;
    const int seg = blk & 7, bh = blk >> 3, h = bh & 31, b = bh >> 5;
    const int tid = threadIdx.x;

    if (tid < CC) {
        float s = 0.f;
        int ab = (b*SEQ + tid*LLC)*HH + h;
        for (int l = 0; l < LLC; l++) s += A[ab + l*HH];
        ea[tid] = __expf(s);
    }
    __syncthreads();

    const int e = seg*512 + tid;
    size_t off = ((size_t)(b*CC)*HH + h)*4096 + e;
    float run = 0.f;
    float v = g_states[off];
    for (int z = 0; z < CC; z++) {
        float nv = (z+1 < CC) ? g_states[off + (size_t)HH*4096] : 0.f;
        g_prefix[off] = run;
        run = run*ea[z] + v;
        v = nv;
        off += (size_t)HH*4096;
    }
}

// ===========================================================================
// K3: Y[l,p] += el[l] * sum_n C[l,n]*St[p,n]; 2x2 warp tiling.
// ===========================================================================
__global__ __launch_bounds__(128) void ssd_k3(
    const float* __restrict__ A, const float* __restrict__ Cm,
    float* __restrict__ Y)
{
    extern __shared__ float smf[];
    u32* sC = (u32*)smf;               // [l][n] skew; later sY stage (plain)
    u32* sS = (u32*)smf + 64*RS;       // [p][n] skew
    float* aA = smf + 2*64*RS;
    float* el = aA + 64;
    float* sY = (float*)sC;

    const int h = blockIdx.x, c = blockIdx.y, b = blockIdx.z;
    const int tid = threadIdx.x, wid = tid >> 5, lane = tid & 31;
    const int qr = lane >> 2, qc = lane & 3;
    const int rh = wid >> 1, ch = wid & 1;
    const int rA0 = rh*32, rA1 = rh*32 + 16;
    const int cB = ch*32;
    const int base = ((b*SEQ + c*LLC)*HH + h)*64;
    const int sbase = ((b*CC + c)*HH + h)*4096;

    #pragma unroll
    for (int i = tid; i < 1024; i += 128) {
        int row = i >> 4, c4 = (i & 15) << 2;
        float4 cv = *(const float4*)&Cm[base + row*GSTR + c4];
        float4 sv = *(const float4*)&g_prefix[sbase + row*64 + c4];
        stp(sC, row, c4+0, cvt_tf32(cv.x)); stp(sC, row, c4+1, cvt_tf32(cv.y));
        stp(sC, row, c4+2, cvt_tf32(cv.z)); stp(sC, row, c4+3, cvt_tf32(cv.w));
        stp(sS, row, c4+0, cvt_tf32(sv.x)); stp(sS, row, c4+1, cvt_tf32(sv.y));
        stp(sS, row, c4+2, cvt_tf32(sv.z)); stp(sS, row, c4+3, cvt_tf32(sv.w));
    }
    if (tid < 64) aA[tid] = A[(b*SEQ + c*LLC + tid)*HH + h];
    __syncthreads();
    if (tid < 64) {
        float s = 0.f, mine = 0.f;
        #pragma unroll
        for (int j = 0; j < 64; j++) { s += aA[j]; if (j == tid) mine = s; }
        el[tid] = __expf(mine);
    }
    __syncthreads();

    float y[2][4][4] = {};
    #pragma unroll
    for (int kk = 0; kk < 8; kk++) {
        u32 a0[4], a1[4];
        ldfragA(sC, rA0+qr, kk, qc, a0);
        ldfragA(sC, rA1+qr, kk, qc, a1);
        #pragma unroll
        for (int t = 0; t < 4; t++) {
            uint2 bb = ldpair(sS, cB + t*8 + qr, kk, qc);
            mma8(y[0][t], a0, bb.x, bb.y);
            mma8(y[1][t], a1, bb.x, bb.y);
        }
    }
    __syncthreads();   // all reads of sC done before restage

    #pragma unroll
    for (int mg = 0; mg < 2; mg++) {
        int r0 = rh*32 + mg*16;
        float e0 = el[r0+qr], e1 = el[r0+qr+8];
        #pragma unroll
        for (int t = 0; t < 4; t++) {
            int c0 = cB + t*8 + 2*qc;
            *(float2*)&sY[(r0+qr)*RS + c0]   = make_float2(e0*y[mg][t][0], e0*y[mg][t][1]);
            *(float2*)&sY[(r0+qr+8)*RS + c0] = make_float2(e1*y[mg][t][2], e1*y[mg][t][3]);
        }
    }
    __syncthreads();

    #pragma unroll
    for (int i = tid; i < 1024; i += 128) {
        int row = i >> 4, c4 = (i & 15) << 2;
        float4 o = *(float4*)&Y[base + row*GSTR + c4];
        float4 a4 = *(const float4*)&sY[row*RS + c4];
        o.x += a4.x; o.y += a4.y; o.z += a4.z; o.w += a4.w;
        *(float4*)&Y[base + row*GSTR + c4] = o;
    }
}

// ---------------------------------------------------------------------------
extern "C" void kernel_launch(void* const* d_in, const int* in_sizes, int n_in,
                              void* d_out, int out_size)
{
    const float* X  = (const float*)d_in[0];
    const float* A  = (const float*)d_in[1];
    const float* Bm = (const float*)d_in[2];
    const float* Cm = (const float*)d_in[3];
    float* Y = (float*)d_out;

    const int sm1 = (3*64*RS + 4*64) * 4;   // 56320 B -> 4 blocks/SM
    const int sm3 = (2*64*RS + 2*64) * 4;   // 37376 B -> 6 blocks/SM
    cudaFuncSetAttribute(ssd_k1, cudaFuncAttributeMaxDynamicSharedMemorySize, sm1);
    cudaFuncSetAttribute(ssd_k3, cudaFuncAttributeMaxDynamicSharedMemorySize, sm3);

    dim3 grid(HH, CC, BS);
    ssd_k1<<<grid, 128, sm1>>>(X, A, Bm, Cm, Y);
    ssd_k2<<<BS*HH*8, 512>>>(A);
    ssd_k3<<<grid, 128, sm3>>>(A, Cm, Y);
}